// round 6
// baseline (speedup 1.0000x reference)
#include <cuda_runtime.h>
#include <cuda_bf16.h>

// Problem constants (fixed by the dataset)
#define B_COLS   64            // dense columns
#define N_MAX    50048         // neuron count (50000) rounded up a bit
#define NNZ_MAX  800000

// Scratch (no allocation allowed): ping-pong buffers + CSR row pointer
__device__ float g_bufX[N_MAX * B_COLS];
__device__ float g_bufY[N_MAX * B_COLS];
__device__ int   g_row_ptr[N_MAX + 1];

// ---------------------------------------------------------------------------
// Build CSR row_ptr from the sorted `rows` array.
// ---------------------------------------------------------------------------
__global__ void build_row_ptr_kernel(const int* __restrict__ rows, int nnz, int n,
                                     int* __restrict__ row_ptr) {
    int i = blockIdx.x * blockDim.x + threadIdx.x;
    if (i >= nnz) return;
    int r = rows[i];
    int rprev = (i == 0) ? -1 : rows[i - 1];
    for (int rr = rprev + 1; rr <= r; rr++) row_ptr[rr] = i;
    if (i == nnz - 1) {
        for (int rr = r + 1; rr <= n; rr++) row_ptr[rr] = nnz;
    }
}

// ---------------------------------------------------------------------------
// CSR SpMM: out[r, :] = sum_e vals[e] * x[cols[e], :]  (+ bias[r] if HAS_BIAS)
// One warp per row (grid-stride over rows), lane l owns dense cols {2l,2l+1}.
//
// This round: latency-exposure fix. __launch_bounds__(256,4) gives ptxas a
// 64-reg budget so the 8 independent float2 gathers in the unrolled body can
// genuinely co-reside in flight (MLP_eff ~8 instead of reg-starved ~3).
// Four accumulators break the dependent-FFMA chain. Grid-stride smooths
// row-length imbalance across a fixed 1184-block grid.
// ---------------------------------------------------------------------------
template <bool HAS_BIAS>
__global__ void __launch_bounds__(256, 4)
spmm_kernel(const float* __restrict__ vals, const int* __restrict__ cols,
            const int* __restrict__ row_ptr, const float* __restrict__ xin,
            const float* __restrict__ bias, float* __restrict__ out, int n) {
    const int lane   = threadIdx.x & 31;
    const int warpId = (blockIdx.x * blockDim.x + threadIdx.x) >> 5;
    const int nWarps = (gridDim.x * blockDim.x) >> 5;

    const float2* __restrict__ x2 = reinterpret_cast<const float2*>(xin) + lane;

    for (int row = warpId; row < n; row += nWarps) {
        int s = row_ptr[row];
        int e = row_ptr[row + 1];

        float ax0 = 0.f, ay0 = 0.f, ax1 = 0.f, ay1 = 0.f;

        int k = s;
        // Peel to 4-edge alignment so float4/int4 metadata loads are 16B aligned.
        while (k < e && (k & 3)) {
            float v = vals[k];
            int   c = cols[k];
            float2 a = x2[c * 32];
            ax0 = fmaf(v, a.x, ax0); ay0 = fmaf(v, a.y, ay0);
            k++;
        }

        // Main body: 8 edges/iter, 8 independent gathers issued before any
        // consumption; two accumulator pairs (even/odd 4-edge groups).
        for (; k + 8 <= e; k += 8) {
            float4 v0 = *reinterpret_cast<const float4*>(vals + k);
            float4 v1 = *reinterpret_cast<const float4*>(vals + k + 4);
            int4   c0 = *reinterpret_cast<const int4*>(cols + k);
            int4   c1 = *reinterpret_cast<const int4*>(cols + k + 4);
            float2 a0 = x2[c0.x * 32];
            float2 a1 = x2[c0.y * 32];
            float2 a2 = x2[c0.z * 32];
            float2 a3 = x2[c0.w * 32];
            float2 a4 = x2[c1.x * 32];
            float2 a5 = x2[c1.y * 32];
            float2 a6 = x2[c1.z * 32];
            float2 a7 = x2[c1.w * 32];
            ax0 = fmaf(v0.x, a0.x, ax0); ay0 = fmaf(v0.x, a0.y, ay0);
            ax1 = fmaf(v0.y, a1.x, ax1); ay1 = fmaf(v0.y, a1.y, ay1);
            ax0 = fmaf(v0.z, a2.x, ax0); ay0 = fmaf(v0.z, a2.y, ay0);
            ax1 = fmaf(v0.w, a3.x, ax1); ay1 = fmaf(v0.w, a3.y, ay1);
            ax0 = fmaf(v1.x, a4.x, ax0); ay0 = fmaf(v1.x, a4.y, ay0);
            ax1 = fmaf(v1.y, a5.x, ax1); ay1 = fmaf(v1.y, a5.y, ay1);
            ax0 = fmaf(v1.z, a6.x, ax0); ay0 = fmaf(v1.z, a6.y, ay0);
            ax1 = fmaf(v1.w, a7.x, ax1); ay1 = fmaf(v1.w, a7.y, ay1);
        }

        // 4-edge group
        for (; k + 4 <= e; k += 4) {
            float4 v0 = *reinterpret_cast<const float4*>(vals + k);
            int4   c0 = *reinterpret_cast<const int4*>(cols + k);
            float2 a0 = x2[c0.x * 32];
            float2 a1 = x2[c0.y * 32];
            float2 a2 = x2[c0.z * 32];
            float2 a3 = x2[c0.w * 32];
            ax0 = fmaf(v0.x, a0.x, ax0); ay0 = fmaf(v0.x, a0.y, ay0);
            ax1 = fmaf(v0.y, a1.x, ax1); ay1 = fmaf(v0.y, a1.y, ay1);
            ax0 = fmaf(v0.z, a2.x, ax0); ay0 = fmaf(v0.z, a2.y, ay0);
            ax1 = fmaf(v0.w, a3.x, ax1); ay1 = fmaf(v0.w, a3.y, ay1);
        }

        // Scalar tail
        for (; k < e; k++) {
            float v = vals[k];
            int   c = cols[k];
            float2 a = x2[c * 32];
            ax0 = fmaf(v, a.x, ax0); ay0 = fmaf(v, a.y, ay0);
        }

        float accx = ax0 + ax1;
        float accy = ay0 + ay1;
        if (HAS_BIAS) {
            float b = bias[row];
            accx += b; accy += b;
        }
        float2 r; r.x = accx; r.y = accy;
        (reinterpret_cast<float2*>(out) + lane)[row * 32] = r;
    }
}

extern "C" void kernel_launch(void* const* d_in, const int* in_sizes, int n_in,
                              void* d_out, int out_size) {
    const float* x        = (const float*)d_in[0];   // [N, 64]
    const float* adj_vals = (const float*)d_in[1];   // [NNZ]
    const float* w_vals   = (const float*)d_in[2];   // [NNZ]
    const float* bias     = (const float*)d_in[3];   // [N]
    const int*   rows     = (const int*)d_in[4];     // [NNZ] sorted
    const int*   cols     = (const int*)d_in[5];     // [NNZ]
    // n_layers (d_in[6]) lives on device; the problem fixes it at 3.

    const int N   = in_sizes[0] / B_COLS;
    const int NNZ = in_sizes[1];

    float* bufX = nullptr; float* bufY = nullptr; int* row_ptr = nullptr;
    cudaGetSymbolAddress((void**)&bufX, g_bufX);
    cudaGetSymbolAddress((void**)&bufY, g_bufY);
    cudaGetSymbolAddress((void**)&row_ptr, g_row_ptr);

    float* outp = (float*)d_out;

    // 1) row_ptr
    {
        int threads = 256;
        int blocks = (NNZ + threads - 1) / threads;
        build_row_ptr_kernel<<<blocks, threads>>>(rows, NNZ, N, row_ptr);
    }

    // 2) three layers, two SpMMs each; last write goes to d_out
    const int threads = 256;
    const int blocks  = 1184;   // 8 blocks/SM worth of warps, grid-stride over rows

    // layer 1
    spmm_kernel<false><<<blocks, threads>>>(w_vals,   cols, row_ptr, x,    nullptr, bufY, N);
    spmm_kernel<true ><<<blocks, threads>>>(adj_vals, cols, row_ptr, bufY, bias,    bufX, N);
    // layer 2
    spmm_kernel<false><<<blocks, threads>>>(w_vals,   cols, row_ptr, bufX, nullptr, bufY, N);
    spmm_kernel<true ><<<blocks, threads>>>(adj_vals, cols, row_ptr, bufY, bias,    bufX, N);
    // layer 3
    spmm_kernel<false><<<blocks, threads>>>(w_vals,   cols, row_ptr, bufX, nullptr, bufY, N);
    spmm_kernel<true ><<<blocks, threads>>>(adj_vals, cols, row_ptr, bufY, bias,    outp, N);
}

// round 7
// speedup vs baseline: 1.3187x; 1.3187x over previous
#include <cuda_runtime.h>
#include <cuda_bf16.h>

// Problem constants (fixed by the dataset)
#define B_COLS   64            // dense columns
#define N_MAX    50048         // neuron count (50000) rounded up a bit
#define NNZ_MAX  800000

// Scratch (no allocation allowed): ping-pong buffers + CSR row pointer
__device__ float g_bufX[N_MAX * B_COLS];
__device__ float g_bufY[N_MAX * B_COLS];
__device__ int   g_row_ptr[N_MAX + 1];

// ---------------------------------------------------------------------------
// Build CSR row_ptr from the sorted `rows` array.
// ---------------------------------------------------------------------------
__global__ void build_row_ptr_kernel(const int* __restrict__ rows, int nnz, int n,
                                     int* __restrict__ row_ptr) {
    int i = blockIdx.x * blockDim.x + threadIdx.x;
    if (i >= nnz) return;
    int r = rows[i];
    int rprev = (i == 0) ? -1 : rows[i - 1];
    for (int rr = rprev + 1; rr <= r; rr++) row_ptr[rr] = i;
    if (i == nnz - 1) {
        for (int rr = r + 1; rr <= n; rr++) row_ptr[rr] = nnz;
    }
}

// ---------------------------------------------------------------------------
// CSR SpMM: out[r, :] = sum_e vals[e] * x[cols[e], :]  (+ bias[r] if HAS_BIAS)
// One warp per row (grid-stride), lane l owns dense cols {2l,2l+1} as float2.
//
// Operating point (learned R2 vs R6): TLP >> ILP here. __launch_bounds__(256,8)
// hard-caps ptxas at 32 regs so 64 warps/SM can co-reside (occ -> ~100%).
// Grid = exactly one resident wave (1184 blocks = 8/SM); grid-stride over rows
// removes the 5.28-wave quantization of the one-row-per-warp launch and
// amortizes row-length imbalance. Inner body identical to the proven R2 body
// (which compiled to 32 regs): 8 edges/iter, vectorized uniform metadata,
// 8 independent 256B gathers in flight.
// ---------------------------------------------------------------------------
template <bool HAS_BIAS>
__global__ void __launch_bounds__(256, 8)
spmm_kernel(const float* __restrict__ vals, const int* __restrict__ cols,
            const int* __restrict__ row_ptr, const float* __restrict__ xin,
            const float* __restrict__ bias, float* __restrict__ out, int n) {
    const int lane   = threadIdx.x & 31;
    const int warpId = (blockIdx.x * blockDim.x + threadIdx.x) >> 5;
    const int nWarps = (gridDim.x * blockDim.x) >> 5;

    const float2* __restrict__ x2 = reinterpret_cast<const float2*>(xin);

    for (int row = warpId; row < n; row += nWarps) {
        int s = row_ptr[row];
        int e = row_ptr[row + 1];

        float accx = 0.0f, accy = 0.0f;

        int k = s;
        // Peel to 4-edge alignment so float4/int4 metadata loads are 16B aligned.
        while (k < e && (k & 3)) {
            float v = vals[k];
            int   c = cols[k];
            float2 a = x2[c * 32 + lane];
            accx = fmaf(v, a.x, accx); accy = fmaf(v, a.y, accy);
            k++;
        }

        // Main body: 8 edges/iter — 2 float4 + 2 int4 uniform metadata loads,
        // 8 independent float2 gathers in flight.
        for (; k + 8 <= e; k += 8) {
            float4 v0 = *reinterpret_cast<const float4*>(vals + k);
            float4 v1 = *reinterpret_cast<const float4*>(vals + k + 4);
            int4   c0 = *reinterpret_cast<const int4*>(cols + k);
            int4   c1 = *reinterpret_cast<const int4*>(cols + k + 4);
            float2 a0 = x2[c0.x * 32 + lane];
            float2 a1 = x2[c0.y * 32 + lane];
            float2 a2 = x2[c0.z * 32 + lane];
            float2 a3 = x2[c0.w * 32 + lane];
            float2 a4 = x2[c1.x * 32 + lane];
            float2 a5 = x2[c1.y * 32 + lane];
            float2 a6 = x2[c1.z * 32 + lane];
            float2 a7 = x2[c1.w * 32 + lane];
            accx = fmaf(v0.x, a0.x, accx); accy = fmaf(v0.x, a0.y, accy);
            accx = fmaf(v0.y, a1.x, accx); accy = fmaf(v0.y, a1.y, accy);
            accx = fmaf(v0.z, a2.x, accx); accy = fmaf(v0.z, a2.y, accy);
            accx = fmaf(v0.w, a3.x, accx); accy = fmaf(v0.w, a3.y, accy);
            accx = fmaf(v1.x, a4.x, accx); accy = fmaf(v1.x, a4.y, accy);
            accx = fmaf(v1.y, a5.x, accx); accy = fmaf(v1.y, a5.y, accy);
            accx = fmaf(v1.z, a6.x, accx); accy = fmaf(v1.z, a6.y, accy);
            accx = fmaf(v1.w, a7.x, accx); accy = fmaf(v1.w, a7.y, accy);
        }

        // 4-edge group
        for (; k + 4 <= e; k += 4) {
            float4 v0 = *reinterpret_cast<const float4*>(vals + k);
            int4   c0 = *reinterpret_cast<const int4*>(cols + k);
            float2 a0 = x2[c0.x * 32 + lane];
            float2 a1 = x2[c0.y * 32 + lane];
            float2 a2 = x2[c0.z * 32 + lane];
            float2 a3 = x2[c0.w * 32 + lane];
            accx = fmaf(v0.x, a0.x, accx); accy = fmaf(v0.x, a0.y, accy);
            accx = fmaf(v0.y, a1.x, accx); accy = fmaf(v0.y, a1.y, accy);
            accx = fmaf(v0.z, a2.x, accx); accy = fmaf(v0.z, a2.y, accy);
            accx = fmaf(v0.w, a3.x, accx); accy = fmaf(v0.w, a3.y, accy);
        }

        // Scalar tail
        for (; k < e; k++) {
            float v = vals[k];
            int   c = cols[k];
            float2 a = x2[c * 32 + lane];
            accx = fmaf(v, a.x, accx); accy = fmaf(v, a.y, accy);
        }

        if (HAS_BIAS) {
            float b = bias[row];
            accx += b; accy += b;
        }
        float2 r; r.x = accx; r.y = accy;
        reinterpret_cast<float2*>(out)[row * 32 + lane] = r;
    }
}

extern "C" void kernel_launch(void* const* d_in, const int* in_sizes, int n_in,
                              void* d_out, int out_size) {
    const float* x        = (const float*)d_in[0];   // [N, 64]
    const float* adj_vals = (const float*)d_in[1];   // [NNZ]
    const float* w_vals   = (const float*)d_in[2];   // [NNZ]
    const float* bias     = (const float*)d_in[3];   // [N]
    const int*   rows     = (const int*)d_in[4];     // [NNZ] sorted
    const int*   cols     = (const int*)d_in[5];     // [NNZ]
    // n_layers (d_in[6]) lives on device; the problem fixes it at 3.

    const int N   = in_sizes[0] / B_COLS;
    const int NNZ = in_sizes[1];

    float* bufX = nullptr; float* bufY = nullptr; int* row_ptr = nullptr;
    cudaGetSymbolAddress((void**)&bufX, g_bufX);
    cudaGetSymbolAddress((void**)&bufY, g_bufY);
    cudaGetSymbolAddress((void**)&row_ptr, g_row_ptr);

    float* outp = (float*)d_out;

    // 1) row_ptr
    {
        int threads = 256;
        int blocks = (NNZ + threads - 1) / threads;
        build_row_ptr_kernel<<<blocks, threads>>>(rows, NNZ, N, row_ptr);
    }

    // 2) three layers, two SpMMs each; last write goes to d_out.
    // One resident wave: 148 SMs x 8 blocks of 256 thr (32 regs cap) = full RF.
    const int threads = 256;
    const int blocks  = 1184;

    // layer 1
    spmm_kernel<false><<<blocks, threads>>>(w_vals,   cols, row_ptr, x,    nullptr, bufY, N);
    spmm_kernel<true ><<<blocks, threads>>>(adj_vals, cols, row_ptr, bufY, bias,    bufX, N);
    // layer 2
    spmm_kernel<false><<<blocks, threads>>>(w_vals,   cols, row_ptr, bufX, nullptr, bufY, N);
    spmm_kernel<true ><<<blocks, threads>>>(adj_vals, cols, row_ptr, bufY, bias,    bufX, N);
    // layer 3
    spmm_kernel<false><<<blocks, threads>>>(w_vals,   cols, row_ptr, bufX, nullptr, bufY, N);
    spmm_kernel<true ><<<blocks, threads>>>(adj_vals, cols, row_ptr, bufY, bias,    outp, N);
}